// round 1
// baseline (speedup 1.0000x reference)
#include <cuda_runtime.h>
#include <math.h>

#define R_ROIS   128
#define C_CH     512
#define HW       32
#define ROI      7
#define FLATK    25088      // 512*7*7
#define HID      4096
#define NLOC     84         // 21*4
#define NSCORE   21
#define MAX_SPLIT 8

// -------- scratch (static device globals; no runtime allocation) --------
__device__ float g_flat[R_ROIS * FLATK];              // pooled+flattened  (12.8 MB)
__device__ float g_fc6 [R_ROIS * HID];
__device__ float g_fc7 [R_ROIS * HID];
__device__ float g_part[MAX_SPLIT * R_ROIS * HID];    // split-K partials (16.8 MB)

// ======================= RoI max pool (torchvision quantized) =======================
__global__ void roi_pool_kernel(const float* __restrict__ x,
                                const float* __restrict__ rois,
                                const int*   __restrict__ roi_idx) {
    int i = blockIdx.x * blockDim.x + threadIdx.x;
    if (i >= R_ROIS * FLATK) return;
    int pw = i % ROI;
    int ph = (i / ROI) % ROI;
    int c  = (i / (ROI * ROI)) % C_CH;
    int r  = i / FLATK;

    // reference swaps rois[:, [1,0,3,2]] -> (x1,y1,x2,y2)
    float y1 = rois[r * 4 + 0];
    float x1 = rois[r * 4 + 1];
    float y2 = rois[r * 4 + 2];
    float x2 = rois[r * 4 + 3];

    // jnp.round == round-half-to-even == rintf (device default rounding)
    float sw = rintf(x1 * 0.0625f);
    float sh = rintf(y1 * 0.0625f);
    float ew = rintf(x2 * 0.0625f);
    float eh = rintf(y2 * 0.0625f);
    float bin_w = fmaxf(ew - sw + 1.0f, 1.0f) * (1.0f / (float)ROI);
    float bin_h = fmaxf(eh - sh + 1.0f, 1.0f) * (1.0f / (float)ROI);

    int ws = (int)fminf(fmaxf(floorf((float)pw        * bin_w) + sw, 0.0f), 32.0f);
    int we = (int)fminf(fmaxf(ceilf ((float)(pw + 1)  * bin_w) + sw, 0.0f), 32.0f);
    int hs = (int)fminf(fmaxf(floorf((float)ph        * bin_h) + sh, 0.0f), 32.0f);
    int he = (int)fminf(fmaxf(ceilf ((float)(ph + 1)  * bin_h) + sh, 0.0f), 32.0f);

    float out = 0.0f;
    if (we > ws && he > hs) {
        const float* f = x + ((size_t)roi_idx[r] * C_CH + c) * (HW * HW);
        float m = -3.402823466e38f;
        for (int h = hs; h < he; h++) {
            const float* row = f + h * HW;
            for (int w = ws; w < we; w++) m = fmaxf(m, row[w]);
        }
        out = m;
    }
    g_flat[i] = out;
}

// ======================= split-K fp32 GEMM (M=128 fixed, N=4096 fixed) =======================
// C_partial[split] = A[128, K-chunk] @ B[K-chunk, 4096] for one 64-wide N tile.
#define BM 128
#define BN 64
#define BK 16
#define TM 8
#define TN 4

__device__ __forceinline__ void gemm_body(const float* __restrict__ A,
                                          const float* __restrict__ B,
                                          int K, int kChunk) {
    __shared__ float As[BK][BM];
    __shared__ float Bs[BK][BN];

    const int n0    = blockIdx.x * BN;
    const int split = blockIdx.y;
    const int k0    = split * kChunk;
    const int k1    = min(K, k0 + kChunk);
    const int tid   = threadIdx.x;
    const int tx    = tid & 15;   // N dir (16 lanes * TN=4 -> 64)
    const int ty    = tid >> 4;   // M dir (16 rows * TM=8 -> 128)

    float acc[TM][TN];
#pragma unroll
    for (int i = 0; i < TM; i++)
#pragma unroll
        for (int j = 0; j < TN; j++) acc[i][j] = 0.0f;

    for (int kb = k0; kb < k1; kb += BK) {
        // A tile: 128x16, A row-major lda=K.  512 float4, 2 per thread.
#pragma unroll
        for (int q = 0; q < 2; q++) {
            int f  = tid + q * 256;
            int m  = f >> 2;
            int kq = (f & 3) * 4;
            float4 v = *(const float4*)(A + (size_t)m * K + kb + kq);
            As[kq + 0][m] = v.x;
            As[kq + 1][m] = v.y;
            As[kq + 2][m] = v.z;
            As[kq + 3][m] = v.w;
        }
        // B tile: 16x64, B row-major ldb=HID. 256 float4, 1 per thread.
        {
            int kk = tid >> 4;
            int nq = (tid & 15) * 4;
            float4 v = *(const float4*)(B + (size_t)(kb + kk) * HID + n0 + nq);
            *(float4*)&Bs[kk][nq] = v;
        }
        __syncthreads();

#pragma unroll
        for (int kk = 0; kk < BK; kk++) {
            float4 a0 = *(const float4*)&As[kk][ty * TM];
            float4 a1 = *(const float4*)&As[kk][ty * TM + 4];
            float4 bv = *(const float4*)&Bs[kk][tx * TN];
            float a[TM] = {a0.x, a0.y, a0.z, a0.w, a1.x, a1.y, a1.z, a1.w};
            float b[TN] = {bv.x, bv.y, bv.z, bv.w};
#pragma unroll
            for (int i = 0; i < TM; i++)
#pragma unroll
                for (int j = 0; j < TN; j++)
                    acc[i][j] = fmaf(a[i], b[j], acc[i][j]);
        }
        __syncthreads();
    }

    float* P = g_part + (size_t)split * R_ROIS * HID;
#pragma unroll
    for (int i = 0; i < TM; i++) {
        int m = ty * TM + i;
#pragma unroll
        for (int j = 0; j < TN; j++) {
            P[(size_t)m * HID + n0 + tx * TN + j] = acc[i][j];
        }
    }
}

__global__ void __launch_bounds__(256) gemm_fc6_kernel(const float* __restrict__ W1) {
    gemm_body(g_flat, W1, FLATK, FLATK / 8);   // 8 splits, 3136 each (196 BK iters)
}
__global__ void __launch_bounds__(256) gemm_fc7_kernel(const float* __restrict__ W2) {
    gemm_body(g_fc6, W2, HID, HID / 4);        // 4 splits, 1024 each
}

// ======================= split-K reduce + bias + relu =======================
__global__ void reduce_fc6_kernel(const float* __restrict__ b1) {
    int i = blockIdx.x * blockDim.x + threadIdx.x;
    if (i >= R_ROIS * HID) return;
    float s = 0.0f;
#pragma unroll
    for (int q = 0; q < 8; q++) s += g_part[(size_t)q * R_ROIS * HID + i];
    s += b1[i & (HID - 1)];
    g_fc6[i] = fmaxf(s, 0.0f);
}
__global__ void reduce_fc7_kernel(const float* __restrict__ b2) {
    int i = blockIdx.x * blockDim.x + threadIdx.x;
    if (i >= R_ROIS * HID) return;
    float s = 0.0f;
#pragma unroll
    for (int q = 0; q < 4; q++) s += g_part[(size_t)q * R_ROIS * HID + i];
    s += b2[i & (HID - 1)];
    g_fc7[i] = fmaxf(s, 0.0f);
}

// ======================= heads: locs [128,84] then scores [128,21] =======================
__global__ void heads_kernel(const float* __restrict__ Wl, const float* __restrict__ bl,
                             const float* __restrict__ Ws, const float* __restrict__ bs,
                             float* __restrict__ out) {
    int r = blockIdx.x;
    int t = threadIdx.x;
    const float* a = g_fc7 + (size_t)r * HID;
    if (t < NLOC) {
        float acc0 = 0.0f, acc1 = 0.0f;
        for (int k = 0; k < HID; k += 2) {
            acc0 = fmaf(a[k],     Wl[(size_t)k       * NLOC + t], acc0);
            acc1 = fmaf(a[k + 1], Wl[(size_t)(k + 1) * NLOC + t], acc1);
        }
        out[(size_t)r * NLOC + t] = acc0 + acc1 + bl[t];
    } else if (t < NLOC + NSCORE) {
        int n = t - NLOC;
        float acc0 = 0.0f, acc1 = 0.0f;
        for (int k = 0; k < HID; k += 2) {
            acc0 = fmaf(a[k],     Ws[(size_t)k       * NSCORE + n], acc0);
            acc1 = fmaf(a[k + 1], Ws[(size_t)(k + 1) * NSCORE + n], acc1);
        }
        out[(size_t)R_ROIS * NLOC + (size_t)r * NSCORE + n] = acc0 + acc1 + bs[n];
    }
}

// ======================= launch =======================
extern "C" void kernel_launch(void* const* d_in, const int* in_sizes, int n_in,
                              void* d_out, int out_size) {
    const float* x    = (const float*)d_in[0];
    const float* rois = (const float*)d_in[1];
    const int*   idx  = (const int*)  d_in[2];
    const float* W1   = (const float*)d_in[3];
    const float* b1   = (const float*)d_in[4];
    const float* W2   = (const float*)d_in[5];
    const float* b2   = (const float*)d_in[6];
    const float* Wl   = (const float*)d_in[7];
    const float* bl   = (const float*)d_in[8];
    const float* Ws   = (const float*)d_in[9];
    const float* bs   = (const float*)d_in[10];
    float* out = (float*)d_out;

    // 1) RoI pool -> g_flat [128, 25088]
    {
        int total = R_ROIS * FLATK;
        roi_pool_kernel<<<(total + 255) / 256, 256>>>(x, rois, idx);
    }
    // 2) fc6 = relu(flat @ W1 + b1)
    gemm_fc6_kernel<<<dim3(HID / BN, 8), 256>>>(W1);
    reduce_fc6_kernel<<<(R_ROIS * HID + 255) / 256, 256>>>(b1);
    // 3) fc7 = relu(fc6 @ W2 + b2)
    gemm_fc7_kernel<<<dim3(HID / BN, 4), 256>>>(W2);
    reduce_fc7_kernel<<<(R_ROIS * HID + 255) / 256, 256>>>(b2);
    // 4) heads -> out = [locs 128*84 | scores 128*21]
    heads_kernel<<<R_ROIS, 128>>>(Wl, bl, Ws, bs, out);
}

// round 4
// speedup vs baseline: 1.4230x; 1.4230x over previous
#include <cuda_runtime.h>
#include <math.h>
#include <stdint.h>

#define R_ROIS   128
#define C_CH     512
#define HW       32
#define ROI      7
#define FLATK    25088      // 512*7*7
#define HID      4096
#define NLOC     84
#define NSCORE   21
#define SPLITS   9

// -------- scratch (static device globals; no runtime allocation) --------
__device__ float g_flat[R_ROIS * FLATK];
__device__ float g_fc6 [R_ROIS * HID];
__device__ float g_fc7 [R_ROIS * HID];
__device__ float g_part[SPLITS * R_ROIS * HID];

// ============================ helpers ============================
__device__ __forceinline__ uint32_t f2tf32(float x) {
    uint32_t r; asm("cvt.rna.tf32.f32 %0, %1;" : "=r"(r) : "f"(x)); return r;
}

__device__ __forceinline__ void mma8(float* d,
                                     uint32_t a0, uint32_t a1, uint32_t a2, uint32_t a3,
                                     uint32_t b0, uint32_t b1) {
    asm volatile(
        "mma.sync.aligned.m16n8k8.row.col.f32.tf32.tf32.f32 "
        "{%0,%1,%2,%3}, {%4,%5,%6,%7}, {%8,%9}, {%0,%1,%2,%3};"
        : "+f"(d[0]), "+f"(d[1]), "+f"(d[2]), "+f"(d[3])
        : "r"(a0), "r"(a1), "r"(a2), "r"(a3), "r"(b0), "r"(b1));
}

// SMEM tile geometry (floats). Interleaved-pair K layout:
//   w(k) = (k>>3)*8 + (k&3)*2 + ((k>>2)&1)   (so (k, k+4) are adjacent -> LDS.64 frags)
#define PITCH        38
#define A_FLOATS     (128 * PITCH)               // 4864
#define B_OFF        (2 * A_FLOATS)              // 9728 (Ahi + Alo)
#define STAGE_FLOATS (B_OFF + 256 * PITCH)       // 19456
#define SMEM_BYTES   (2 * STAGE_FLOATS * 4)      // 155648

__device__ __forceinline__ int kmap(int k) {
    return ((k >> 3) << 3) + ((k & 3) << 1) + ((k >> 2) & 1);
}

// ============================ RoI max pool ============================
__global__ void roi_pool_kernel(const float* __restrict__ x,
                                const float* __restrict__ rois,
                                const int*   __restrict__ roi_idx) {
    int i = blockIdx.x * blockDim.x + threadIdx.x;
    if (i >= R_ROIS * FLATK) return;
    int pw = i % ROI;
    int ph = (i / ROI) % ROI;
    int c  = (i / (ROI * ROI)) % C_CH;
    int r  = i / FLATK;

    float y1 = rois[r * 4 + 0];
    float x1 = rois[r * 4 + 1];
    float y2 = rois[r * 4 + 2];
    float x2 = rois[r * 4 + 3];

    float sw = rintf(x1 * 0.0625f);
    float sh = rintf(y1 * 0.0625f);
    float ew = rintf(x2 * 0.0625f);
    float eh = rintf(y2 * 0.0625f);
    float bin_w = fmaxf(ew - sw + 1.0f, 1.0f) * (1.0f / (float)ROI);
    float bin_h = fmaxf(eh - sh + 1.0f, 1.0f) * (1.0f / (float)ROI);

    int ws = (int)fminf(fmaxf(floorf((float)pw       * bin_w) + sw, 0.0f), 32.0f);
    int we = (int)fminf(fmaxf(ceilf ((float)(pw + 1) * bin_w) + sw, 0.0f), 32.0f);
    int hs = (int)fminf(fmaxf(floorf((float)ph       * bin_h) + sh, 0.0f), 32.0f);
    int he = (int)fminf(fmaxf(ceilf ((float)(ph + 1) * bin_h) + sh, 0.0f), 32.0f);

    float out = 0.0f;
    if (we > ws && he > hs) {
        const float* f = x + ((size_t)roi_idx[r] * C_CH + c) * (HW * HW);
        float m = -3.402823466e38f;
        for (int h = hs; h < he; h++) {
            const float* row = f + h * HW;
            for (int w = ws; w < we; w++) m = fmaxf(m, row[w]);
        }
        out = m;
    }
    g_flat[i] = out;
}

// ============================ tf32 mma.sync split-K GEMM ============================
// C[128, 4096] partials = A[128,K] @ W[K,4096].  CTA tile M128 x N256 x K32.
// A is split into tf32 hi+lo (fp32-accurate A side); B raw tf32.
// 512 threads = 16 warps laid out 4(M) x 2(N); warp tile 32x64 via m16n8k8.

__device__ __forceinline__ void ldg_stage(const float* __restrict__ A, int lda,
                                          const float* __restrict__ W, int n0,
                                          int kb, int tid, float4* rA, float* rB) {
#pragma unroll
    for (int q = 0; q < 2; q++) {
        int f = tid + q * 512;
        int m = f >> 3;
        int c = f & 7;
        rA[q] = *(const float4*)(A + (size_t)m * lda + kb + c * 4);
    }
    int n  = tid & 255;
    int kg = tid >> 8;
#pragma unroll
    for (int j = 0; j < 16; j++) {
        int k = kg * 16 + j;
        rB[j] = W[(size_t)(kb + k) * HID + n0 + n];
    }
}

__device__ __forceinline__ void sts_stage(float* st, int tid, const float4* rA, const float* rB) {
    float* Ahi = st;
    float* Alo = st + A_FLOATS;
    float* Bs  = st + B_OFF;
#pragma unroll
    for (int q = 0; q < 2; q++) {
        int f = tid + q * 512;
        int m = f >> 3;
        int c = f & 7;
        float v[4] = {rA[q].x, rA[q].y, rA[q].z, rA[q].w};
#pragma unroll
        for (int e = 0; e < 4; e++) {
            int k = c * 4 + e;
            int w = kmap(k);
            uint32_t hb = f2tf32(v[e]);
            Ahi[m * PITCH + w] = __uint_as_float(hb);
            Alo[m * PITCH + w] = __uint_as_float(f2tf32(v[e] - __uint_as_float(hb)));
        }
    }
    int n  = tid & 255;
    int kg = tid >> 8;
#pragma unroll
    for (int j = 0; j < 16; j++) {
        int k = kg * 16 + j;
        Bs[n * PITCH + kmap(k)] = __uint_as_float(f2tf32(rB[j]));
    }
}

__global__ void __launch_bounds__(512, 1) gemm_tc_kernel(const float* __restrict__ W,
                                                         int which, int iters_per_split) {
    extern __shared__ float sm[];
    const float* A = which ? g_fc6 : g_flat;
    const int lda  = which ? HID : FLATK;
    const int totIters = lda / 32;

    const int tid   = threadIdx.x;
    const int wid   = tid >> 5;
    const int lane  = tid & 31;
    const int g     = lane >> 2;
    const int t     = lane & 3;
    const int m0    = (wid & 3) * 32;
    const int nw    = (wid >> 2) * 64;
    const int n0    = blockIdx.x * 256;
    const int split = blockIdx.y;
    const int it0   = split * iters_per_split;
    const int nIt   = min(iters_per_split, totIters - it0);

    float acc[2][8][4];
#pragma unroll
    for (int i = 0; i < 2; i++)
#pragma unroll
        for (int j = 0; j < 8; j++)
#pragma unroll
            for (int e = 0; e < 4; e++) acc[i][j][e] = 0.0f;

    float4 rA[2];
    float  rB[16];

    ldg_stage(A, lda, W, n0, it0 * 32, tid, rA, rB);
    sts_stage(sm, tid, rA, rB);
    __syncthreads();

    for (int it = 0; it < nIt; it++) {
        const float* cur = sm + (size_t)(it & 1) * STAGE_FLOATS;
        bool more = (it + 1) < nIt;
        if (more) ldg_stage(A, lda, W, n0, (it0 + it + 1) * 32, tid, rA, rB);

        const float* Ah = cur;
        const float* Al = cur + A_FLOATS;
        const float* Bs = cur + B_OFF;

#pragma unroll
        for (int ks = 0; ks < 4; ks++) {
            const int ko = ks * 8 + t * 2;
            float2 h0a = *(const float2*)(Ah + (m0 + g     ) * PITCH + ko);
            float2 h0b = *(const float2*)(Ah + (m0 + g +  8) * PITCH + ko);
            float2 h1a = *(const float2*)(Ah + (m0 + g + 16) * PITCH + ko);
            float2 h1b = *(const float2*)(Ah + (m0 + g + 24) * PITCH + ko);
            float2 l0a = *(const float2*)(Al + (m0 + g     ) * PITCH + ko);
            float2 l0b = *(const float2*)(Al + (m0 + g +  8) * PITCH + ko);
            float2 l1a = *(const float2*)(Al + (m0 + g + 16) * PITCH + ko);
            float2 l1b = *(const float2*)(Al + (m0 + g + 24) * PITCH + ko);
#pragma unroll
            for (int j = 0; j < 8; j++) {
                float2 bv = *(const float2*)(Bs + (nw + j * 8 + g) * PITCH + ko);
                uint32_t b0 = __float_as_uint(bv.x);
                uint32_t b1 = __float_as_uint(bv.y);
                mma8(acc[0][j], __float_as_uint(h0a.x), __float_as_uint(h0b.x),
                                __float_as_uint(h0a.y), __float_as_uint(h0b.y), b0, b1);
                mma8(acc[0][j], __float_as_uint(l0a.x), __float_as_uint(l0b.x),
                                __float_as_uint(l0a.y), __float_as_uint(l0b.y), b0, b1);
                mma8(acc[1][j], __float_as_uint(h1a.x), __float_as_uint(h1b.x),
                                __float_as_uint(h1a.y), __float_as_uint(h1b.y), b0, b1);
                mma8(acc[1][j], __float_as_uint(l1a.x), __float_as_uint(l1b.x),
                                __float_as_uint(l1a.y), __float_as_uint(l1b.y), b0, b1);
            }
        }

        if (more) sts_stage(sm + (size_t)((it + 1) & 1) * STAGE_FLOATS, tid, rA, rB);
        __syncthreads();
    }

    // epilogue -> split-K partials
    float* P = g_part + (size_t)split * (R_ROIS * HID);
#pragma unroll
    for (int i = 0; i < 2; i++) {
        int row = m0 + i * 16 + g;
#pragma unroll
        for (int j = 0; j < 8; j++) {
            int col = n0 + nw + j * 8 + t * 2;
            *(float2*)&P[(size_t)row * HID + col] =
                make_float2(acc[i][j][0], acc[i][j][1]);
            *(float2*)&P[(size_t)(row + 8) * HID + col] =
                make_float2(acc[i][j][2], acc[i][j][3]);
        }
    }
}

// ============================ split-K reduce + bias + relu ============================
__global__ void reduce_fc6_kernel(const float* __restrict__ b1) {
    int i = blockIdx.x * blockDim.x + threadIdx.x;
    if (i >= R_ROIS * HID) return;
    float s = 0.0f;
#pragma unroll
    for (int q = 0; q < SPLITS; q++) s += g_part[(size_t)q * R_ROIS * HID + i];
    s += b1[i & (HID - 1)];
    g_fc6[i] = fmaxf(s, 0.0f);
}
__global__ void reduce_fc7_kernel(const float* __restrict__ b2) {
    int i = blockIdx.x * blockDim.x + threadIdx.x;
    if (i >= R_ROIS * HID) return;
    float s = 0.0f;
#pragma unroll
    for (int q = 0; q < SPLITS; q++) s += g_part[(size_t)q * R_ROIS * HID + i];
    s += b2[i & (HID - 1)];
    g_fc7[i] = fmaxf(s, 0.0f);
}

// ============================ heads ============================
__global__ void heads_kernel(const float* __restrict__ Wl, const float* __restrict__ bl,
                             const float* __restrict__ Ws, const float* __restrict__ bs,
                             float* __restrict__ out) {
    int r = blockIdx.x;
    int t = threadIdx.x;
    const float* a = g_fc7 + (size_t)r * HID;
    if (t < NLOC) {
        float acc0 = 0.0f, acc1 = 0.0f;
        for (int k = 0; k < HID; k += 2) {
            acc0 = fmaf(a[k],     Wl[(size_t)k       * NLOC + t], acc0);
            acc1 = fmaf(a[k + 1], Wl[(size_t)(k + 1) * NLOC + t], acc1);
        }
        out[(size_t)r * NLOC + t] = acc0 + acc1 + bl[t];
    } else if (t < NLOC + NSCORE) {
        int n = t - NLOC;
        float acc0 = 0.0f, acc1 = 0.0f;
        for (int k = 0; k < HID; k += 2) {
            acc0 = fmaf(a[k],     Ws[(size_t)k       * NSCORE + n], acc0);
            acc1 = fmaf(a[k + 1], Ws[(size_t)(k + 1) * NSCORE + n], acc1);
        }
        out[(size_t)R_ROIS * NLOC + (size_t)r * NSCORE + n] = acc0 + acc1 + bs[n];
    }
}

// ============================ launch ============================
extern "C" void kernel_launch(void* const* d_in, const int* in_sizes, int n_in,
                              void* d_out, int out_size) {
    const float* x    = (const float*)d_in[0];
    const float* rois = (const float*)d_in[1];
    const int*   idx  = (const int*)  d_in[2];
    const float* W1   = (const float*)d_in[3];
    const float* b1   = (const float*)d_in[4];
    const float* W2   = (const float*)d_in[5];
    const float* b2   = (const float*)d_in[6];
    const float* Wl   = (const float*)d_in[7];
    const float* bl   = (const float*)d_in[8];
    const float* Ws   = (const float*)d_in[9];
    const float* bs   = (const float*)d_in[10];
    float* out = (float*)d_out;

    static int smem_set = 0;
    if (!smem_set) {
        cudaFuncSetAttribute(gemm_tc_kernel, cudaFuncAttributeMaxDynamicSharedMemorySize, SMEM_BYTES);
        smem_set = 1;
    }

    // 1) RoI pool -> g_flat [128, 25088]
    roi_pool_kernel<<<(R_ROIS * FLATK + 255) / 256, 256>>>(x, rois, idx);

    // 2) fc6: K=25088 -> 784 K32-iters, 9 splits of <=88 ; grid 16 x 9 = 144 CTAs
    gemm_tc_kernel<<<dim3(HID / 256, SPLITS), 512, SMEM_BYTES>>>(W1, 0, 88);
    reduce_fc6_kernel<<<(R_ROIS * HID + 255) / 256, 256>>>(b1);

    // 3) fc7: K=4096 -> 128 iters, 9 splits of <=15
    gemm_tc_kernel<<<dim3(HID / 256, SPLITS), 512, SMEM_BYTES>>>(W2, 1, 15);
    reduce_fc7_kernel<<<(R_ROIS * HID + 255) / 256, 256>>>(b2);

    // 4) heads -> out = [locs 128*84 | scores 128*21]
    heads_kernel<<<R_ROIS, 128>>>(Wl, bl, Ws, bs, out);
}

// round 6
// speedup vs baseline: 3.9070x; 2.7456x over previous
#include <cuda_runtime.h>
#include <math.h>
#include <stdint.h>

#define R_ROIS   128
#define C_CH     512
#define HW       32
#define ROI      7
#define FLATK    25088      // 512*7*7
#define HID      4096
#define NLOC     84
#define NSCORE   21
#define SPLITS   9
#define HOUT     105        // 84 + 21
#define HSPLITS  128        // heads split-K count (K32 each)

// -------- scratch (static device globals; no runtime allocation) --------
__device__ float g_flat[R_ROIS * FLATK];
__device__ float g_fc6 [R_ROIS * HID];
__device__ float g_fc7 [R_ROIS * HID];
__device__ float g_part[SPLITS * R_ROIS * HID];   // also reused for heads partials

// ============================ helpers ============================
__device__ __forceinline__ uint32_t smem_u32(const void* p) {
    uint32_t a;
    asm("{ .reg .u64 t; cvta.to.shared.u64 t, %1; cvt.u32.u64 %0, t; }" : "=r"(a) : "l"(p));
    return a;
}
__device__ __forceinline__ uint32_t f2tf32(float x) {
    uint32_t r; asm("cvt.rna.tf32.f32 %0, %1;" : "=r"(r) : "f"(x)); return r;
}
__device__ __forceinline__ void cp16(uint32_t dst, const void* src) {
    asm volatile("cp.async.cg.shared.global [%0], [%1], 16;" :: "r"(dst), "l"(src));
}
__device__ __forceinline__ void cp_commit() { asm volatile("cp.async.commit_group;"); }
__device__ __forceinline__ void cp_wait0()  { asm volatile("cp.async.wait_group 0;" ::: "memory"); }

__device__ __forceinline__ void mma8(float* d,
                                     uint32_t a0, uint32_t a1, uint32_t a2, uint32_t a3,
                                     uint32_t b0, uint32_t b1) {
    asm volatile(
        "mma.sync.aligned.m16n8k8.row.col.f32.tf32.tf32.f32 "
        "{%0,%1,%2,%3}, {%4,%5,%6,%7}, {%8,%9}, {%0,%1,%2,%3};"
        : "+f"(d[0]), "+f"(d[1]), "+f"(d[2]), "+f"(d[3])
        : "r"(a0), "r"(a1), "r"(a2), "r"(a3), "r"(b0), "r"(b1));
}

// SMEM geometry (floats):
//  A: 128 rows x pitch 38, (k,k+4)-interleaved-pair layout, pre-cvt tf32.
//  B: 32 k-rows x pitch 264, raw fp32 (cp.async), cvt at fragment load.
#define PA        38
#define PB        264
#define A_WORDS   (128 * PA)              // 4864
#define B_OFFW    A_WORDS
#define STAGE_W   (A_WORDS + 32 * PB)     // 13312 floats = 53248 B
#define SMEM_BYTES (2 * STAGE_W * 4)      // 106496

// ============================ RoI max pool ============================
__global__ void roi_pool_kernel(const float* __restrict__ x,
                                const float* __restrict__ rois,
                                const int*   __restrict__ roi_idx) {
    int i = blockIdx.x * blockDim.x + threadIdx.x;
    if (i >= R_ROIS * FLATK) return;
    int pw = i % ROI;
    int ph = (i / ROI) % ROI;
    int c  = (i / (ROI * ROI)) % C_CH;
    int r  = i / FLATK;

    float y1 = rois[r * 4 + 0];
    float x1 = rois[r * 4 + 1];
    float y2 = rois[r * 4 + 2];
    float x2 = rois[r * 4 + 3];

    float sw = rintf(x1 * 0.0625f);
    float sh = rintf(y1 * 0.0625f);
    float ew = rintf(x2 * 0.0625f);
    float eh = rintf(y2 * 0.0625f);
    float bin_w = fmaxf(ew - sw + 1.0f, 1.0f) * (1.0f / (float)ROI);
    float bin_h = fmaxf(eh - sh + 1.0f, 1.0f) * (1.0f / (float)ROI);

    int ws = (int)fminf(fmaxf(floorf((float)pw       * bin_w) + sw, 0.0f), 32.0f);
    int we = (int)fminf(fmaxf(ceilf ((float)(pw + 1) * bin_w) + sw, 0.0f), 32.0f);
    int hs = (int)fminf(fmaxf(floorf((float)ph       * bin_h) + sh, 0.0f), 32.0f);
    int he = (int)fminf(fmaxf(ceilf ((float)(ph + 1) * bin_h) + sh, 0.0f), 32.0f);

    int spanW = we - ws;
    float out = 0.0f;
    if (spanW > 0 && he > hs) {
        const float* f = x + ((size_t)roi_idx[r] * C_CH + c) * (HW * HW);
        float m = -3.402823466e38f;
        for (int h = hs; h < he; h++) {
            const float* row = f + h * HW + ws;
#pragma unroll
            for (int dw = 0; dw < 6; dw++)
                if (dw < spanW) m = fmaxf(m, row[dw]);
        }
        out = m;
    }
    g_flat[i] = out;
}

// ============================ tf32 mma.sync split-K GEMM ============================
// CTA tile M128 x N256 x K32; 256 threads = 8 warps 2(M) x 4(N); warp tile 64x64.
// Single rna-tf32 A (pre-converted in SMEM); B raw via cp.async, cvt.rna at frag time.

__device__ __forceinline__ void ldgA(float4* ra, const float* __restrict__ A,
                                     int am, int lda, int kpos) {
    const float* p = A + (size_t)am * lda + kpos;
    ra[0] = *(const float4*)(p);
    ra[1] = *(const float4*)(p + 4);
    ra[2] = *(const float4*)(p + 8);
    ra[3] = *(const float4*)(p + 12);
}

__device__ __forceinline__ void stsA(float* stage, int am, int ah, const float4* ra) {
    float* dst = stage + am * PA + ah;
    const float* v0 = (const float*)&ra[0];
    const float* v1 = (const float*)&ra[1];
    const float* v2 = (const float*)&ra[2];
    const float* v3 = (const float*)&ra[3];
#pragma unroll
    for (int c = 0; c < 4; c++) {
        float2 p0, p1;
        p0.x = __uint_as_float(f2tf32(v0[c]));
        p0.y = __uint_as_float(f2tf32(v1[c]));
        p1.x = __uint_as_float(f2tf32(v2[c]));
        p1.y = __uint_as_float(f2tf32(v3[c]));
        *(float2*)(dst + 2 * c)     = p0;     // pair (k=ah+c,   k=ah+c+4)
        *(float2*)(dst + 8 + 2 * c) = p1;     // pair (k=ah+8+c, k=ah+12+c)
    }
}

__device__ __forceinline__ void cpB(uint32_t sB, const float* __restrict__ Wm,
                                    int kb, int n0, int bnq, int bk0) {
#pragma unroll
    for (int j = 0; j < 8; j++) {
        int k = bk0 + j * 4;
        const float* src = Wm + (size_t)(kb + k) * HID + n0 + bnq;
        cp16(sB + (uint32_t)(k * PB + bnq) * 4, src);
    }
    cp_commit();
}

__device__ __forceinline__ void compute_stage(const float* st, float acc[4][8][4],
                                              int m0, int nw, int g, int t) {
    const float* Ab = st;
    const float* Bb = st + A_WORDS;
#pragma unroll
    for (int ks = 0; ks < 4; ks++) {
        float2 pa[4], pb[4];
#pragma unroll
        for (int mi = 0; mi < 4; mi++) {
            int row = m0 + mi * 16 + g;
            pa[mi] = *(const float2*)(Ab + row * PA + ks * 8 + t * 2);
            pb[mi] = *(const float2*)(Ab + (row + 8) * PA + ks * 8 + t * 2);
        }
        const float* brow0 = Bb + (ks * 8 + t) * PB + nw + g;
        const float* brow1 = brow0 + 4 * PB;
#pragma unroll
        for (int j = 0; j < 8; j++) {
            uint32_t b0 = f2tf32(brow0[j * 8]);
            uint32_t b1 = f2tf32(brow1[j * 8]);
#pragma unroll
            for (int mi = 0; mi < 4; mi++)
                mma8(acc[mi][j],
                     __float_as_uint(pa[mi].x), __float_as_uint(pb[mi].x),
                     __float_as_uint(pa[mi].y), __float_as_uint(pb[mi].y),
                     b0, b1);
        }
    }
}

__global__ void __launch_bounds__(256, 1) gemm_tc_kernel(const float* __restrict__ Wm,
                                                         int which, int iters_per_split) {
    extern __shared__ float sm[];
    const float* A = which ? g_fc6 : g_flat;
    const int lda  = which ? HID : FLATK;
    const int totIters = lda / 32;

    const int tid  = threadIdx.x;
    const int lane = tid & 31, wid = tid >> 5;
    const int g    = lane >> 2, t = lane & 3;
    const int m0   = (wid & 1) * 64;
    const int nw   = (wid >> 1) * 64;
    const int n0   = blockIdx.x * 256;
    const int it0  = blockIdx.y * iters_per_split;
    const int nIt  = min(iters_per_split, totIters - it0);

    const int am  = tid >> 1;
    const int ah  = (tid & 1) << 4;
    const int bnq = (tid & 63) << 2;
    const int bk0 = tid >> 6;
    const uint32_t sb = smem_u32(sm);

    float acc[4][8][4];
#pragma unroll
    for (int mi = 0; mi < 4; mi++)
#pragma unroll
        for (int j = 0; j < 8; j++)
#pragma unroll
            for (int e = 0; e < 4; e++) acc[mi][j][e] = 0.0f;

    float4 ra[4];

    // prologue: fill stage 0
    ldgA(ra, A, am, lda, it0 * 32 + ah);
    cpB(sb + (uint32_t)B_OFFW * 4, Wm, it0 * 32, n0, bnq, bk0);
    stsA(sm, am, ah, ra);
    cp_wait0();
    __syncthreads();

    for (int it = 0; it < nIt; it++) {
        float* cur = sm + (size_t)(it & 1) * STAGE_W;
        float* nxt = sm + (size_t)((it + 1) & 1) * STAGE_W;
        bool more = (it + 1) < nIt;
        if (more) {
            int kb = (it0 + it + 1) * 32;
            ldgA(ra, A, am, lda, kb + ah);
            cpB(sb + (uint32_t)(((it + 1) & 1) * STAGE_W + B_OFFW) * 4, Wm, kb, n0, bnq, bk0);
        }
        compute_stage(cur, acc, m0, nw, g, t);
        if (more) stsA(nxt, am, ah, ra);
        cp_wait0();
        __syncthreads();
    }

    // epilogue -> split-K partials
    float* P = g_part + (size_t)blockIdx.y * (R_ROIS * HID);
#pragma unroll
    for (int mi = 0; mi < 4; mi++) {
        int row = m0 + mi * 16 + g;
#pragma unroll
        for (int j = 0; j < 8; j++) {
            int col = n0 + nw + j * 8 + t * 2;
            *(float2*)&P[(size_t)row * HID + col]       = make_float2(acc[mi][j][0], acc[mi][j][1]);
            *(float2*)&P[(size_t)(row + 8) * HID + col] = make_float2(acc[mi][j][2], acc[mi][j][3]);
        }
    }
}

// ============================ split-K reduce + bias + relu ============================
__global__ void reduce_fc6_kernel(const float* __restrict__ b1) {
    int i = blockIdx.x * blockDim.x + threadIdx.x;
    if (i >= R_ROIS * HID) return;
    float s = 0.0f;
#pragma unroll
    for (int q = 0; q < SPLITS; q++) s += g_part[(size_t)q * R_ROIS * HID + i];
    s += b1[i & (HID - 1)];
    g_fc6[i] = fmaxf(s, 0.0f);
}
__global__ void reduce_fc7_kernel(const float* __restrict__ b2) {
    int i = blockIdx.x * blockDim.x + threadIdx.x;
    if (i >= R_ROIS * HID) return;
    float s = 0.0f;
#pragma unroll
    for (int q = 0; q < SPLITS; q++) s += g_part[(size_t)q * R_ROIS * HID + i];
    s += b2[i & (HID - 1)];
    g_fc7[i] = fmaxf(s, 0.0f);
}

// ============================ heads: split-K mini-GEMM ============================
// C[128,105] = fc7[128,4096] @ [Wl | Ws].  128 splits of K32 -> g_part, then reduce.
__global__ void __launch_bounds__(512) heads_gemm_kernel(const float* __restrict__ Wl,
                                                         const float* __restrict__ Ws) {
    __shared__ float As[128 * 33];
    __shared__ float Wt[32 * 106];
    const int s   = blockIdx.x;
    const int k0  = s * 32;
    const int tid = threadIdx.x;

    for (int i = tid; i < 128 * 32; i += 512) {
        int r = i >> 5, k = i & 31;
        As[r * 33 + k] = g_fc7[(size_t)r * HID + k0 + k];
    }
    for (int i = tid; i < 32 * HOUT; i += 512) {
        int k = i / HOUT, n = i % HOUT;
        Wt[k * 106 + n] = (n < NLOC) ? Wl[(size_t)(k0 + k) * NLOC + n]
                                     : Ws[(size_t)(k0 + k) * NSCORE + (n - NLOC)];
    }
    __syncthreads();

    int rg = tid >> 4;        // 0..31 -> rows rg*4..rg*4+3
    int ng = tid & 15;        // 0..15; ng<15 active -> cols ng*7..ng*7+6
    if (ng < 15) {
        float acc[4][7];
#pragma unroll
        for (int rr = 0; rr < 4; rr++)
#pragma unroll
            for (int jj = 0; jj < 7; jj++) acc[rr][jj] = 0.0f;

        for (int k = 0; k < 32; k++) {
            float w[7], a[4];
#pragma unroll
            for (int jj = 0; jj < 7; jj++) w[jj] = Wt[k * 106 + ng * 7 + jj];
#pragma unroll
            for (int rr = 0; rr < 4; rr++) a[rr] = As[(rg * 4 + rr) * 33 + k];
#pragma unroll
            for (int rr = 0; rr < 4; rr++)
#pragma unroll
                for (int jj = 0; jj < 7; jj++)
                    acc[rr][jj] = fmaf(a[rr], w[jj], acc[rr][jj]);
        }
        float* P = g_part + (size_t)s * (R_ROIS * HOUT);
#pragma unroll
        for (int rr = 0; rr < 4; rr++)
#pragma unroll
            for (int jj = 0; jj < 7; jj++)
                P[(rg * 4 + rr) * HOUT + ng * 7 + jj] = acc[rr][jj];
    }
}

__global__ void heads_reduce_kernel(const float* __restrict__ bl,
                                    const float* __restrict__ bs,
                                    float* __restrict__ out) {
    int i = blockIdx.x * blockDim.x + threadIdx.x;
    if (i >= R_ROIS * HOUT) return;
    int r = i / HOUT, n = i % HOUT;
    float s = 0.0f;
    for (int q = 0; q < HSPLITS; q++) s += g_part[(size_t)q * (R_ROIS * HOUT) + i];
    if (n < NLOC) {
        out[(size_t)r * NLOC + n] = s + bl[n];
    } else {
        out[(size_t)R_ROIS * NLOC + (size_t)r * NSCORE + (n - NLOC)] = s + bs[n - NLOC];
    }
}

// ============================ launch ============================
extern "C" void kernel_launch(void* const* d_in, const int* in_sizes, int n_in,
                              void* d_out, int out_size) {
    const float* x    = (const float*)d_in[0];
    const float* rois = (const float*)d_in[1];
    const int*   idx  = (const int*)  d_in[2];
    const float* W1   = (const float*)d_in[3];
    const float* b1   = (const float*)d_in[4];
    const float* W2   = (const float*)d_in[5];
    const float* b2   = (const float*)d_in[6];
    const float* Wl   = (const float*)d_in[7];
    const float* bl   = (const float*)d_in[8];
    const float* Ws   = (const float*)d_in[9];
    const float* bs   = (const float*)d_in[10];
    float* out = (float*)d_out;

    cudaFuncSetAttribute(gemm_tc_kernel, cudaFuncAttributeMaxDynamicSharedMemorySize, SMEM_BYTES);

    // 1) RoI pool -> g_flat [128, 25088]
    roi_pool_kernel<<<(R_ROIS * FLATK + 255) / 256, 256>>>(x, rois, idx);

    // 2) fc6: K=25088 -> 784 K32-iters, 9 splits of <=88; grid 16 x 9
    gemm_tc_kernel<<<dim3(HID / 256, SPLITS), 256, SMEM_BYTES>>>(W1, 0, 88);
    reduce_fc6_kernel<<<(R_ROIS * HID + 255) / 256, 256>>>(b1);

    // 3) fc7: K=4096 -> 128 iters, 9 splits of <=15
    gemm_tc_kernel<<<dim3(HID / 256, SPLITS), 256, SMEM_BYTES>>>(W2, 1, 15);
    reduce_fc7_kernel<<<(R_ROIS * HID + 255) / 256, 256>>>(b2);

    // 4) heads: 128-split mini-GEMM + reduce -> out = [locs 128*84 | scores 128*21]
    heads_gemm_kernel<<<HSPLITS, 512>>>(Wl, Ws);
    heads_reduce_kernel<<<(R_ROIS * HOUT + 255) / 256, 256>>>(bl, bs, out);
}